// round 1
// baseline (speedup 1.0000x reference)
#include <cuda_runtime.h>
#include <cstddef>

#define D 128
#define MAXN 50176

// ---- scratch (allocation-free rule: __device__ globals) ----
__device__ __align__(16) float g_xh  [(size_t)MAXN * D];
__device__ __align__(16) float g_tx1 [(size_t)MAXN * D];
__device__ __align__(16) float g_msum[(size_t)MAXN * D];
__device__ __align__(16) float g_o12 [(size_t)MAXN * D];
__device__ float g_deg [MAXN];
__device__ float g_cnt [MAXN];
__device__ float g_dis [MAXN];
__device__ float g_invc[MAXN];

__device__ __forceinline__ void red_add_f4(float* p, float4 v) {
    asm volatile("red.global.add.v4.f32 [%0], {%1,%2,%3,%4};"
                 :: "l"(p), "f"(v.x), "f"(v.y), "f"(v.z), "f"(v.w) : "memory");
}

// ---- zero accumulators ----
__global__ void k_zero(int n) {
    int stride = gridDim.x * blockDim.x;
    int i = blockIdx.x * blockDim.x + threadIdx.x;
    int tot4 = n * D / 4;
    float4 z = make_float4(0.f, 0.f, 0.f, 0.f);
    for (int idx = i; idx < tot4; idx += stride) {
        ((float4*)g_tx1)[idx]  = z;
        ((float4*)g_msum)[idx] = z;
    }
    for (int idx = i; idx < n; idx += stride) { g_deg[idx] = 0.f; g_cnt[idx] = 0.f; }
}

// ---- per-edge scalar reductions: weighted out-degree (src), in-count (dst) ----
__global__ void k_edge_scalar(const int* __restrict__ src, const int* __restrict__ dst,
                              const float* __restrict__ w, int E) {
    int e = blockIdx.x * blockDim.x + threadIdx.x;
    if (e < E) {
        atomicAdd(&g_deg[src[e]], w[e]);
        atomicAdd(&g_cnt[dst[e]], 1.0f);
    }
}

// ---- per-node: dis = deg>0 ? rsqrt(deg) : 0 ;  invc = 1/max(cnt,1) ----
__global__ void k_node_prep(int n) {
    int i = blockIdx.x * blockDim.x + threadIdx.x;
    if (i < n) {
        float d = g_deg[i];
        g_dis[i]  = d > 0.f ? rsqrtf(d) : 0.f;
        g_invc[i] = 1.0f / fmaxf(g_cnt[i], 1.0f);
    }
}

// ---- fused edge feature scatter: one warp per edge, reads xh[src] once,
//      red.v4 into Tx1 (Cheb norm-scaled) and msum (weight-scaled) ----
__global__ void k_edge_scatter(const int* __restrict__ src, const int* __restrict__ dst,
                               const float* __restrict__ w, int E) {
    int e = (blockIdx.x * blockDim.x + threadIdx.x) >> 5;
    if (e >= E) return;
    int lane = threadIdx.x & 31;
    int s  = __ldg(src + e);
    int d2 = __ldg(dst + e);
    float ew = __ldg(w + e);
    float cn = -g_dis[s] * ew * g_dis[d2];
    float4 v = *((const float4*)g_xh + (size_t)s * 32 + lane);
    red_add_f4((float*)((float4*)g_tx1 + (size_t)d2 * 32 + lane),
               make_float4(cn * v.x, cn * v.y, cn * v.z, cn * v.w));
    red_add_f4((float*)((float4*)g_msum + (size_t)d2 * 32 + lane),
               make_float4(ew * v.x, ew * v.y, ew * v.z, ew * v.w));
}

// ---- generic 128-wide GEMM: C[m][o] = sum_k A[m][k]*W[o][k] + bias[o] ----
// BM=64, BN=128, BK=16, 256 threads, thread tile 8x4.
__global__ __launch_bounds__(256) void k_gemm_single(
    const float* __restrict__ A, const float* __restrict__ W,
    const float* __restrict__ bias, float* __restrict__ C, int n)
{
    __shared__ __align__(16) float As[16][68];
    __shared__ __align__(16) float Bs[16][128];
    int m0 = blockIdx.x * 64;
    int tid = threadIdx.x;
    int ty = tid >> 5, lane = tid & 31;
    int row0 = ty * 8, col0 = lane * 4;
    int ar = tid >> 2, ac = (tid & 3) * 4;
    int bn = tid >> 1, bcc = (tid & 1) * 8;
    bool arok = (m0 + ar) < n;

    float acc[8][4];
#pragma unroll
    for (int i = 0; i < 8; i++)
#pragma unroll
        for (int j = 0; j < 4; j++) acc[i][j] = 0.f;

    for (int kc = 0; kc < 128; kc += 16) {
        float4 av = make_float4(0.f, 0.f, 0.f, 0.f);
        if (arok) av = *(const float4*)(A + (size_t)(m0 + ar) * 128 + kc + ac);
        As[ac + 0][ar] = av.x; As[ac + 1][ar] = av.y;
        As[ac + 2][ar] = av.z; As[ac + 3][ar] = av.w;
        float4 b0 = *(const float4*)(W + (size_t)bn * 128 + kc + bcc);
        float4 b1 = *(const float4*)(W + (size_t)bn * 128 + kc + bcc + 4);
        Bs[bcc + 0][bn] = b0.x; Bs[bcc + 1][bn] = b0.y; Bs[bcc + 2][bn] = b0.z; Bs[bcc + 3][bn] = b0.w;
        Bs[bcc + 4][bn] = b1.x; Bs[bcc + 5][bn] = b1.y; Bs[bcc + 6][bn] = b1.z; Bs[bcc + 7][bn] = b1.w;
        __syncthreads();
#pragma unroll
        for (int k = 0; k < 16; k++) {
            float4 alo = *(const float4*)&As[k][row0];
            float4 ahi = *(const float4*)&As[k][row0 + 4];
            float4 bv  = *(const float4*)&Bs[k][col0];
            float a[8] = {alo.x, alo.y, alo.z, alo.w, ahi.x, ahi.y, ahi.z, ahi.w};
            float b[4] = {bv.x, bv.y, bv.z, bv.w};
#pragma unroll
            for (int i = 0; i < 8; i++)
#pragma unroll
                for (int j = 0; j < 4; j++)
                    acc[i][j] = fmaf(a[i], b[j], acc[i][j]);
        }
        __syncthreads();
    }
    float4 bv4 = *(const float4*)(bias + col0);
    float bb[4] = {bv4.x, bv4.y, bv4.z, bv4.w};
#pragma unroll
    for (int i = 0; i < 8; i++) {
        int m = m0 + row0 + i;
        if (m < n) {
            float4 o;
            o.x = acc[i][0] + bb[0]; o.y = acc[i][1] + bb[1];
            o.z = acc[i][2] + bb[2]; o.w = acc[i][3] + bb[3];
            *(float4*)(C + (size_t)m * 128 + col0) = o;
        }
    }
}

// ---- fused middle stage: o12 = lrelu(xh@Wc0'+Tx1@Wc1'+bc) + lrelu(mean@Wrel'+xh@Wroot'+brel)
__global__ __launch_bounds__(256) void k_gemm_main(int n,
    const float* __restrict__ Wc0, const float* __restrict__ Wc1,
    const float* __restrict__ Wrel, const float* __restrict__ Wroot,
    const float* __restrict__ bcb, const float* __restrict__ brel)
{
    __shared__ __align__(16) float Axh[16][68];
    __shared__ __align__(16) float Atx[16][68];
    __shared__ __align__(16) float Amn[16][68];
    __shared__ __align__(16) float B0[16][128];
    __shared__ __align__(16) float B1[16][128];
    __shared__ __align__(16) float B2[16][128];
    __shared__ __align__(16) float B3[16][128];

    int m0 = blockIdx.x * 64;
    int tid = threadIdx.x;
    int ty = tid >> 5, lane = tid & 31;
    int row0 = ty * 8, col0 = lane * 4;
    int ar = tid >> 2, ac = (tid & 3) * 4;
    int bn = tid >> 1, bcc = (tid & 1) * 8;
    bool arok = (m0 + ar) < n;
    float inv = arok ? g_invc[m0 + ar] : 0.f;
    size_t abase = (size_t)(m0 + ar) * 128;

    float acc1[8][4], acc2[8][4];
#pragma unroll
    for (int i = 0; i < 8; i++)
#pragma unroll
        for (int j = 0; j < 4; j++) { acc1[i][j] = 0.f; acc2[i][j] = 0.f; }

    for (int kc = 0; kc < 128; kc += 16) {
        float4 vx = make_float4(0.f,0.f,0.f,0.f), vt = vx, vm = vx;
        if (arok) {
            vx = *(const float4*)(g_xh   + abase + kc + ac);
            vt = *(const float4*)(g_tx1  + abase + kc + ac);
            vm = *(const float4*)(g_msum + abase + kc + ac);
        }
        Axh[ac+0][ar]=vx.x; Axh[ac+1][ar]=vx.y; Axh[ac+2][ar]=vx.z; Axh[ac+3][ar]=vx.w;
        Atx[ac+0][ar]=vt.x; Atx[ac+1][ar]=vt.y; Atx[ac+2][ar]=vt.z; Atx[ac+3][ar]=vt.w;
        Amn[ac+0][ar]=vm.x*inv; Amn[ac+1][ar]=vm.y*inv; Amn[ac+2][ar]=vm.z*inv; Amn[ac+3][ar]=vm.w*inv;

#define LOADB(BS, WPTR) do { \
        float4 t0 = *(const float4*)((WPTR) + (size_t)bn*128 + kc + bcc); \
        float4 t1 = *(const float4*)((WPTR) + (size_t)bn*128 + kc + bcc + 4); \
        BS[bcc+0][bn]=t0.x; BS[bcc+1][bn]=t0.y; BS[bcc+2][bn]=t0.z; BS[bcc+3][bn]=t0.w; \
        BS[bcc+4][bn]=t1.x; BS[bcc+5][bn]=t1.y; BS[bcc+6][bn]=t1.z; BS[bcc+7][bn]=t1.w; } while(0)
        LOADB(B0, Wc0); LOADB(B1, Wc1); LOADB(B2, Wrel); LOADB(B3, Wroot);
#undef LOADB
        __syncthreads();
#pragma unroll
        for (int k = 0; k < 16; k++) {
            float4 xlo = *(const float4*)&Axh[k][row0];
            float4 xhi = *(const float4*)&Axh[k][row0 + 4];
            float4 tlo = *(const float4*)&Atx[k][row0];
            float4 thi = *(const float4*)&Atx[k][row0 + 4];
            float4 mlo = *(const float4*)&Amn[k][row0];
            float4 mhi = *(const float4*)&Amn[k][row0 + 4];
            float4 w0v = *(const float4*)&B0[k][col0];
            float4 w1v = *(const float4*)&B1[k][col0];
            float4 w2v = *(const float4*)&B2[k][col0];
            float4 w3v = *(const float4*)&B3[k][col0];
            float ax[8] = {xlo.x,xlo.y,xlo.z,xlo.w,xhi.x,xhi.y,xhi.z,xhi.w};
            float at[8] = {tlo.x,tlo.y,tlo.z,tlo.w,thi.x,thi.y,thi.z,thi.w};
            float am[8] = {mlo.x,mlo.y,mlo.z,mlo.w,mhi.x,mhi.y,mhi.z,mhi.w};
            float w0[4] = {w0v.x,w0v.y,w0v.z,w0v.w};
            float w1[4] = {w1v.x,w1v.y,w1v.z,w1v.w};
            float w2[4] = {w2v.x,w2v.y,w2v.z,w2v.w};
            float w3[4] = {w3v.x,w3v.y,w3v.z,w3v.w};
#pragma unroll
            for (int i = 0; i < 8; i++)
#pragma unroll
                for (int j = 0; j < 4; j++) {
                    acc1[i][j] = fmaf(ax[i], w0[j], acc1[i][j]);
                    acc1[i][j] = fmaf(at[i], w1[j], acc1[i][j]);
                    acc2[i][j] = fmaf(am[i], w2[j], acc2[i][j]);
                    acc2[i][j] = fmaf(ax[i], w3[j], acc2[i][j]);
                }
        }
        __syncthreads();
    }
    float4 bc4 = *(const float4*)(bcb + col0);
    float4 br4 = *(const float4*)(brel + col0);
    float bcv[4] = {bc4.x, bc4.y, bc4.z, bc4.w};
    float brv[4] = {br4.x, br4.y, br4.z, br4.w};
#pragma unroll
    for (int i = 0; i < 8; i++) {
        int m = m0 + row0 + i;
        if (m < n) {
            float o[4];
#pragma unroll
            for (int j = 0; j < 4; j++) {
                float v1 = acc1[i][j] + bcv[j];
                float v2 = acc2[i][j] + brv[j];
                v1 = v1 >= 0.f ? v1 : 0.01f * v1;
                v2 = v2 >= 0.f ? v2 : 0.01f * v2;
                o[j] = v1 + v2;
            }
            *(float4*)(g_o12 + (size_t)m * 128 + col0) = make_float4(o[0], o[1], o[2], o[3]);
        }
    }
}

extern "C" void kernel_launch(void* const* d_in, const int* in_sizes, int n_in,
                              void* d_out, int out_size) {
    const float* x     = (const float*)d_in[1];
    const int*   ei    = (const int*)  d_in[2];
    const float* ew    = (const float*)d_in[3];
    const float* Wp    = (const float*)d_in[4];
    const float* bp    = (const float*)d_in[5];
    const float* Wc0   = (const float*)d_in[6];
    const float* Wc1   = (const float*)d_in[7];
    const float* bc    = (const float*)d_in[8];
    const float* Wrel  = (const float*)d_in[9];
    const float* brel  = (const float*)d_in[10];
    const float* Wroot = (const float*)d_in[11];
    const float* Wl    = (const float*)d_in[12];
    const float* bl    = (const float*)d_in[13];

    int n = in_sizes[1] / D;
    int E = in_sizes[3];
    float* out = (float*)d_out;

    void *p_xh = nullptr, *p_o12 = nullptr;
    cudaGetSymbolAddress(&p_xh, g_xh);
    cudaGetSymbolAddress(&p_o12, g_o12);

    // his = x (first half of output)
    cudaMemcpyAsync(out, x, (size_t)n * D * sizeof(float), cudaMemcpyDeviceToDevice, 0);

    k_zero<<<1024, 256>>>(n);

    int gb = (n + 63) / 64;
    k_gemm_single<<<gb, 256>>>(x, Wp, bp, (float*)p_xh, n);          // xh
    k_edge_scalar<<<(E + 255) / 256, 256>>>(ei, ei + E, ew, E);      // deg, cnt
    k_node_prep<<<(n + 255) / 256, 256>>>(n);                        // dis, invc
    k_edge_scatter<<<(E + 7) / 8, 256>>>(ei, ei + E, ew, E);         // Tx1, msum
    k_gemm_main<<<gb, 256>>>(n, Wc0, Wc1, Wrel, Wroot, bc, brel);    // o12
    k_gemm_single<<<gb, 256>>>((const float*)p_o12, Wl, bl,
                               out + (size_t)n * D, n);              // o3
}

// round 4
// speedup vs baseline: 1.1038x; 1.1038x over previous
#include <cuda_runtime.h>
#include <cuda_bf16.h>
#include <cstdint>
#include <cstddef>

#define D 128
#define MAXN 50176

// ================= global scratch (no allocations allowed) =================
__device__ __align__(16) float g_xh  [(size_t)MAXN * D];
__device__ __align__(16) float g_tx1 [(size_t)MAXN * D];
__device__ __align__(16) float g_msum[(size_t)MAXN * D];
__device__ __align__(16) __nv_bfloat16 g_o12h[(size_t)MAXN * D];
__device__ __align__(16) __nv_bfloat16 g_o12l[(size_t)MAXN * D];
__device__ __align__(16) __nv_bfloat16 g_wh[6][D * D];
__device__ __align__(16) __nv_bfloat16 g_wl[6][D * D];
__device__ float g_deg [MAXN];
__device__ float g_cnt [MAXN];
__device__ float g_dis [MAXN];
__device__ float g_invc[MAXN];

enum { WP = 0, WC0, WC1, WREL, WROOT, WLIN };

// ================= warp-MMA helpers (sm_80+ path; no tcgen05) =================
__device__ __forceinline__ uint32_t smem_u32(const void* p) {
    return (uint32_t)__cvta_generic_to_shared(p);
}
// XOR-swizzled byte offset of the 16B chunk (row, c16) in a 128x128 bf16 tile
// (row stride 256B = 16 chunks). Conflict-free for ldmatrix & vector stores.
__device__ __forceinline__ uint32_t sw_off(int row, int c16) {
    return (uint32_t)(row * 256 + ((c16 ^ (row & 7)) << 4));
}
__device__ __forceinline__ void ldx4(uint32_t r[4], uint32_t a) {
    asm volatile("ldmatrix.sync.aligned.m8n8.x4.shared.b16 {%0,%1,%2,%3}, [%4];"
                 : "=r"(r[0]), "=r"(r[1]), "=r"(r[2]), "=r"(r[3]) : "r"(a));
}
__device__ __forceinline__ void mma16816(float c[4], const uint32_t a[4],
                                         uint32_t b0, uint32_t b1) {
    asm volatile("mma.sync.aligned.m16n8k16.row.col.f32.bf16.bf16.f32 "
                 "{%0,%1,%2,%3}, {%4,%5,%6,%7}, {%8,%9}, {%0,%1,%2,%3};"
                 : "+f"(c[0]), "+f"(c[1]), "+f"(c[2]), "+f"(c[3])
                 : "r"(a[0]), "r"(a[1]), "r"(a[2]), "r"(a[3]), "r"(b0), "r"(b1));
}

__device__ __forceinline__ uint32_t pk(__nv_bfloat16 a, __nv_bfloat16 b) {
    return (uint32_t)__bfloat16_as_ushort(a) | ((uint32_t)__bfloat16_as_ushort(b) << 16);
}

// One warp's contribution for one 128x128x128 split-3 product set.
// Warp tile 32(m) x 64(n): 2 m16 tiles x 8 n8 tiles, K=128 in 8 k16 steps.
// acc += Ah*Bh + Ah*Bl + Al*Bh
__device__ __forceinline__ void warp_phase(
    uint32_t aH, uint32_t aL, uint32_t bH, uint32_t bL,
    int m_base, int n_base, int lane, float acc[2][8][4])
{
    int r = lane & 15, chs = lane >> 4;
#pragma unroll
    for (int kk = 0; kk < 8; kk++) {
        int c = 2 * kk + chs;
        uint32_t ah[2][4], al[2][4];
#pragma unroll
        for (int mt = 0; mt < 2; mt++) {
            uint32_t off = sw_off(m_base + mt * 16 + r, c);
            ldx4(ah[mt], aH + off);
            ldx4(al[mt], aL + off);
        }
        uint32_t bh[4][4], bl[4][4];
#pragma unroll
        for (int g = 0; g < 4; g++) {
            uint32_t off = sw_off(n_base + g * 16 + r, c);
            ldx4(bh[g], bH + off);
            ldx4(bl[g], bL + off);
        }
#pragma unroll
        for (int mt = 0; mt < 2; mt++)
#pragma unroll
            for (int j = 0; j < 8; j++) {
                int g = j >> 1, p = j & 1;
                mma16816(acc[mt][j], ah[mt], bh[g][p], bh[g][p + 2]);
                mma16816(acc[mt][j], ah[mt], bl[g][p], bl[g][p + 2]);
                mma16816(acc[mt][j], al[mt], bh[g][p], bh[g][p + 2]);
            }
    }
}

// load 128x128 fp32 tile (row-major, row guard), split to bf16 hi/lo, store swizzled
__device__ __forceinline__ void load_split(const float* __restrict__ src, int m0, int n,
                                           char* ah, char* al,
                                           const float* __restrict__ rowscale, int tid) {
#pragma unroll
    for (int t = 0; t < 8; t++) {
        int idx = tid + t * 256;           // 2048 chunks of 8 floats
        int row = idx >> 4;
        int c16 = idx & 15;
        int gr = m0 + row;
        float4 v0 = make_float4(0.f, 0.f, 0.f, 0.f), v1 = v0;
        float s = 1.f;
        if (gr < n) {
            const float* p = src + (size_t)gr * D + c16 * 8;
            v0 = *(const float4*)p;
            v1 = *(const float4*)(p + 4);
            if (rowscale) s = rowscale[gr];
        }
        v0.x *= s; v0.y *= s; v0.z *= s; v0.w *= s;
        v1.x *= s; v1.y *= s; v1.z *= s; v1.w *= s;
        float f[8] = {v0.x, v0.y, v0.z, v0.w, v1.x, v1.y, v1.z, v1.w};
        __nv_bfloat16 h[8], l[8];
#pragma unroll
        for (int q = 0; q < 8; q++) {
            h[q] = __float2bfloat16(f[q]);
            l[q] = __float2bfloat16(f[q] - __bfloat162float(h[q]));
        }
        uint32_t off = sw_off(row, c16);
        *(uint4*)(ah + off) = make_uint4(pk(h[0], h[1]), pk(h[2], h[3]), pk(h[4], h[5]), pk(h[6], h[7]));
        *(uint4*)(al + off) = make_uint4(pk(l[0], l[1]), pk(l[2], l[3]), pk(l[4], l[5]), pk(l[6], l[7]));
    }
}

// load 128x128 bf16 tile (row-major, row guard) swizzled into smem
__device__ __forceinline__ void load_bf(const __nv_bfloat16* __restrict__ src, int m0,
                                        int nrows, char* dst, int tid) {
#pragma unroll
    for (int t = 0; t < 8; t++) {
        int idx = tid + t * 256;
        int row = idx >> 4;
        int c16 = idx & 15;
        uint4 v = make_uint4(0, 0, 0, 0);
        if (m0 + row < nrows) v = *(const uint4*)(src + (size_t)(m0 + row) * D + c16 * 8);
        *(uint4*)(dst + sw_off(row, c16)) = v;
    }
}

// ================= misc kernels =================
__device__ __forceinline__ void red_add_f4(float* p, float4 v) {
    asm volatile("red.global.add.v4.f32 [%0], {%1,%2,%3,%4};"
                 :: "l"(p), "f"(v.x), "f"(v.y), "f"(v.z), "f"(v.w) : "memory");
}

__global__ void k_zero(int n) {
    int stride = gridDim.x * blockDim.x;
    int i = blockIdx.x * blockDim.x + threadIdx.x;
    int tot4 = n * D / 4;
    float4 z = make_float4(0.f, 0.f, 0.f, 0.f);
    for (int idx = i; idx < tot4; idx += stride) {
        ((float4*)g_tx1)[idx]  = z;
        ((float4*)g_msum)[idx] = z;
    }
    for (int idx = i; idx < n; idx += stride) { g_deg[idx] = 0.f; g_cnt[idx] = 0.f; }
}

__global__ void k_split_w(const float* w0, const float* w1, const float* w2,
                          const float* w3, const float* w4, const float* w5) {
    const float* srcs[6] = {w0, w1, w2, w3, w4, w5};
    int ws = blockIdx.y;
    int i = blockIdx.x * 256 + threadIdx.x;   // 16384 elems
    float v = srcs[ws][i];
    __nv_bfloat16 h = __float2bfloat16(v);
    g_wh[ws][i] = h;
    g_wl[ws][i] = __float2bfloat16(v - __bfloat162float(h));
}

__global__ void k_edge_scalar(const int* __restrict__ src, const int* __restrict__ dst,
                              const float* __restrict__ w, int E) {
    int e = blockIdx.x * blockDim.x + threadIdx.x;
    if (e < E) {
        atomicAdd(&g_deg[src[e]], w[e]);
        atomicAdd(&g_cnt[dst[e]], 1.0f);
    }
}

__global__ void k_node_prep(int n) {
    int i = blockIdx.x * blockDim.x + threadIdx.x;
    if (i < n) {
        float d = g_deg[i];
        g_dis[i]  = d > 0.f ? rsqrtf(d) : 0.f;
        g_invc[i] = 1.0f / fmaxf(g_cnt[i], 1.0f);
    }
}

__global__ void k_edge_scatter(const int* __restrict__ src, const int* __restrict__ dst,
                               const float* __restrict__ w, int E) {
    int e = (blockIdx.x * blockDim.x + threadIdx.x) >> 5;
    if (e >= E) return;
    int lane = threadIdx.x & 31;
    int s  = __ldg(src + e);
    int d2 = __ldg(dst + e);
    float ew = __ldg(w + e);
    float cn = -g_dis[s] * ew * g_dis[d2];
    float4 v = *((const float4*)g_xh + (size_t)s * 32 + lane);
    red_add_f4((float*)((float4*)g_tx1 + (size_t)d2 * 32 + lane),
               make_float4(cn * v.x, cn * v.y, cn * v.z, cn * v.w));
    red_add_f4((float*)((float4*)g_msum + (size_t)d2 * 32 + lane),
               make_float4(ew * v.x, ew * v.y, ew * v.z, ew * v.w));
}

// ================= GEMM kernels =================
// smem: xh/fin: Ah@0 Al@32K Wh@64K Wl@96K  (128KB); mid adds A2h@64K A2l@96K Wh@128K Wl@160K (192KB)
#define SM_XH  (131072 + 1024)
#define SM_MID (196608 + 1024)

// xh = x @ Wp^T + bp   (fp32 out to g_xh)
__global__ __launch_bounds__(256) void k_gemm_xh(const float* __restrict__ x,
                                                 const float* __restrict__ bp, int n) {
    extern __shared__ char dsm[];
    char* sb = (char*)(((uintptr_t)dsm + 1023) & ~(uintptr_t)1023);
    int tid = threadIdx.x, wid = tid >> 5, lane = tid & 31;
    int m0 = blockIdx.x * 128;
    int m_base = (wid & 3) * 32, n_base = (wid >> 2) * 64;

    load_split(x, m0, n, sb, sb + 32768, nullptr, tid);
    load_bf(g_wh[WP], 0, 128, sb + 65536, tid);
    load_bf(g_wl[WP], 0, 128, sb + 98304, tid);
    __syncthreads();

    float acc[2][8][4];
#pragma unroll
    for (int a = 0; a < 2; a++)
#pragma unroll
        for (int b = 0; b < 8; b++)
#pragma unroll
            for (int q = 0; q < 4; q++) acc[a][b][q] = 0.f;

    uint32_t base = smem_u32(sb);
    warp_phase(base, base + 32768, base + 65536, base + 98304, m_base, n_base, lane, acc);

    int rr = lane >> 2, cc = 2 * (lane & 3);
#pragma unroll
    for (int mt = 0; mt < 2; mt++) {
        int row = m0 + m_base + mt * 16 + rr;
#pragma unroll
        for (int j = 0; j < 8; j++) {
            int col = n_base + j * 8 + cc;
            float b0 = __ldg(bp + col), b1 = __ldg(bp + col + 1);
            if (row < n)
                *(float2*)(g_xh + (size_t)row * D + col) =
                    make_float2(acc[mt][j][0] + b0, acc[mt][j][1] + b1);
            if (row + 8 < n)
                *(float2*)(g_xh + (size_t)(row + 8) * D + col) =
                    make_float2(acc[mt][j][2] + b0, acc[mt][j][3] + b1);
        }
    }
}

// middle: acc1 = xh@Wc0^T + Tx1@Wc1^T ; acc2 = xh@Wroot^T + mean@Wrel^T
// o12 = lrelu(acc1+bc) + lrelu(acc2+brel) -> bf16 hi/lo to g_o12h/g_o12l
__global__ __launch_bounds__(256) void k_gemm_mid(const float* __restrict__ bc,
                                                  const float* __restrict__ brel, int n) {
    extern __shared__ char dsm[];
    char* sb = (char*)(((uintptr_t)dsm + 1023) & ~(uintptr_t)1023);
    int tid = threadIdx.x, wid = tid >> 5, lane = tid & 31;
    int m0 = blockIdx.x * 128;
    int m_base = (wid & 3) * 32, n_base = (wid >> 2) * 64;

    char* A1h = sb;           char* A1l = sb + 32768;
    char* A2h = sb + 65536;   char* A2l = sb + 98304;
    char* Wh  = sb + 131072;  char* Wl  = sb + 163840;
    uint32_t a1H = smem_u32(A1h), a1L = a1H + 32768;
    uint32_t a2H = a1H + 65536,   a2L = a1H + 98304;
    uint32_t wH  = a1H + 131072,  wL  = a1H + 163840;

    float acc1[2][8][4], acc2[2][8][4];
#pragma unroll
    for (int a = 0; a < 2; a++)
#pragma unroll
        for (int b = 0; b < 8; b++)
#pragma unroll
            for (int q = 0; q < 4; q++) { acc1[a][b][q] = 0.f; acc2[a][b][q] = 0.f; }

    // phase 0: acc1 = xh @ Wc0
    load_split(g_xh,  m0, n, A1h, A1l, nullptr, tid);
    load_split(g_tx1, m0, n, A2h, A2l, nullptr, tid);
    load_bf(g_wh[WC0], 0, 128, Wh, tid);
    load_bf(g_wl[WC0], 0, 128, Wl, tid);
    __syncthreads();
    warp_phase(a1H, a1L, wH, wL, m_base, n_base, lane, acc1);
    __syncthreads();

    // phase 1: acc1 += Tx1 @ Wc1
    load_bf(g_wh[WC1], 0, 128, Wh, tid);
    load_bf(g_wl[WC1], 0, 128, Wl, tid);
    __syncthreads();
    warp_phase(a2H, a2L, wH, wL, m_base, n_base, lane, acc1);
    __syncthreads();

    // phase 2: acc2 = xh @ Wroot ; reload A2 = mean = msum * invc
    load_bf(g_wh[WROOT], 0, 128, Wh, tid);
    load_bf(g_wl[WROOT], 0, 128, Wl, tid);
    load_split(g_msum, m0, n, A2h, A2l, g_invc, tid);
    __syncthreads();
    warp_phase(a1H, a1L, wH, wL, m_base, n_base, lane, acc2);
    __syncthreads();

    // phase 3: acc2 += mean @ Wrel
    load_bf(g_wh[WREL], 0, 128, Wh, tid);
    load_bf(g_wl[WREL], 0, 128, Wl, tid);
    __syncthreads();
    warp_phase(a2H, a2L, wH, wL, m_base, n_base, lane, acc2);

    int rr = lane >> 2, cc = 2 * (lane & 3);
#pragma unroll
    for (int mt = 0; mt < 2; mt++) {
#pragma unroll
        for (int j = 0; j < 8; j++) {
            int col = n_base + j * 8 + cc;
            float c0 = __ldg(bc + col),   c1 = __ldg(bc + col + 1);
            float r0 = __ldg(brel + col), r1 = __ldg(brel + col + 1);
#pragma unroll
            for (int half = 0; half < 2; half++) {
                int row = m0 + m_base + mt * 16 + rr + half * 8;
                if (row < n) {
                    float v1a = acc1[mt][j][2 * half + 0] + c0;
                    float v1b = acc1[mt][j][2 * half + 1] + c1;
                    float v2a = acc2[mt][j][2 * half + 0] + r0;
                    float v2b = acc2[mt][j][2 * half + 1] + r1;
                    v1a = v1a >= 0.f ? v1a : 0.01f * v1a;
                    v1b = v1b >= 0.f ? v1b : 0.01f * v1b;
                    v2a = v2a >= 0.f ? v2a : 0.01f * v2a;
                    v2b = v2b >= 0.f ? v2b : 0.01f * v2b;
                    float oa = v1a + v2a, ob = v1b + v2b;
                    __nv_bfloat16 ha = __float2bfloat16(oa), hb = __float2bfloat16(ob);
                    __nv_bfloat16 la = __float2bfloat16(oa - __bfloat162float(ha));
                    __nv_bfloat16 lb = __float2bfloat16(ob - __bfloat162float(hb));
                    size_t p = (size_t)row * D + col;
                    *(uint32_t*)(g_o12h + p) = pk(ha, hb);
                    *(uint32_t*)(g_o12l + p) = pk(la, lb);
                }
            }
        }
    }
}

// o3 = o12 @ Wl^T + bl  -> fp32 to out region
__global__ __launch_bounds__(256) void k_gemm_fin(const float* __restrict__ bl,
                                                  float* __restrict__ out2, int n) {
    extern __shared__ char dsm[];
    char* sb = (char*)(((uintptr_t)dsm + 1023) & ~(uintptr_t)1023);
    int tid = threadIdx.x, wid = tid >> 5, lane = tid & 31;
    int m0 = blockIdx.x * 128;
    int m_base = (wid & 3) * 32, n_base = (wid >> 2) * 64;

    load_bf(g_o12h, m0, n, sb, tid);
    load_bf(g_o12l, m0, n, sb + 32768, tid);
    load_bf(g_wh[WLIN], 0, 128, sb + 65536, tid);
    load_bf(g_wl[WLIN], 0, 128, sb + 98304, tid);
    __syncthreads();

    float acc[2][8][4];
#pragma unroll
    for (int a = 0; a < 2; a++)
#pragma unroll
        for (int b = 0; b < 8; b++)
#pragma unroll
            for (int q = 0; q < 4; q++) acc[a][b][q] = 0.f;

    uint32_t base = smem_u32(sb);
    warp_phase(base, base + 32768, base + 65536, base + 98304, m_base, n_base, lane, acc);

    int rr = lane >> 2, cc = 2 * (lane & 3);
#pragma unroll
    for (int mt = 0; mt < 2; mt++) {
        int row = m0 + m_base + mt * 16 + rr;
#pragma unroll
        for (int j = 0; j < 8; j++) {
            int col = n_base + j * 8 + cc;
            float b0 = __ldg(bl + col), b1 = __ldg(bl + col + 1);
            if (row < n)
                *(float2*)(out2 + (size_t)row * D + col) =
                    make_float2(acc[mt][j][0] + b0, acc[mt][j][1] + b1);
            if (row + 8 < n)
                *(float2*)(out2 + (size_t)(row + 8) * D + col) =
                    make_float2(acc[mt][j][2] + b0, acc[mt][j][3] + b1);
        }
    }
}

// ================= launch =================
extern "C" void kernel_launch(void* const* d_in, const int* in_sizes, int n_in,
                              void* d_out, int out_size) {
    const float* x     = (const float*)d_in[1];
    const int*   ei    = (const int*)  d_in[2];
    const float* ew    = (const float*)d_in[3];
    const float* Wp    = (const float*)d_in[4];
    const float* bp    = (const float*)d_in[5];
    const float* Wc0   = (const float*)d_in[6];
    const float* Wc1   = (const float*)d_in[7];
    const float* bc    = (const float*)d_in[8];
    const float* Wrel  = (const float*)d_in[9];
    const float* brel  = (const float*)d_in[10];
    const float* Wroot = (const float*)d_in[11];
    const float* Wl    = (const float*)d_in[12];
    const float* bl    = (const float*)d_in[13];

    int n = in_sizes[1] / D;
    int E = in_sizes[3];
    float* out = (float*)d_out;

    cudaFuncSetAttribute(k_gemm_xh,  cudaFuncAttributeMaxDynamicSharedMemorySize, SM_XH);
    cudaFuncSetAttribute(k_gemm_mid, cudaFuncAttributeMaxDynamicSharedMemorySize, SM_MID);
    cudaFuncSetAttribute(k_gemm_fin, cudaFuncAttributeMaxDynamicSharedMemorySize, SM_XH);

    // his = x (first half of output)
    cudaMemcpyAsync(out, x, (size_t)n * D * sizeof(float), cudaMemcpyDeviceToDevice, 0);

    k_zero<<<1024, 256>>>(n);
    k_split_w<<<dim3(64, 6), 256>>>(Wp, Wc0, Wc1, Wrel, Wroot, Wl);
    k_edge_scalar<<<(E + 255) / 256, 256>>>(ei, ei + E, ew, E);
    k_node_prep<<<(n + 255) / 256, 256>>>(n);

    int grid = (n + 127) / 128;
    k_gemm_xh<<<grid, 256, SM_XH>>>(x, bp, n);
    k_edge_scatter<<<(E + 7) / 8, 256>>>(ei, ei + E, ew, E);
    k_gemm_mid<<<grid, 256, SM_MID>>>(bc, brel, n);
    k_gemm_fin<<<grid, 256, SM_XH>>>(bl, out + (size_t)n * D, n);
}

// round 5
// speedup vs baseline: 1.4220x; 1.2882x over previous
#include <cuda_runtime.h>
#include <cuda_bf16.h>
#include <cstdint>
#include <cstddef>

#define D 128
#define MAXN 50176
#define MAXE 1048576

// ================= global scratch (no allocations allowed) =================
__device__ __align__(16) float g_xh  [(size_t)MAXN * D];
__device__ __align__(16) float g_tx1 [(size_t)MAXN * D];
__device__ __align__(16) float g_msum[(size_t)MAXN * D];
__device__ __align__(16) __nv_bfloat16 g_o12h[(size_t)MAXN * D];
__device__ __align__(16) __nv_bfloat16 g_o12l[(size_t)MAXN * D];
__device__ float g_deg [MAXN];
__device__ float g_dis [MAXN];
__device__ float g_invc[MAXN];
__device__ int   g_hist[MAXN];
__device__ int   g_base[MAXN];
__device__ int   g_cursor[MAXN];
__device__ int   g_esrc[MAXE];
__device__ float g_ews [MAXE];

// ================= warp-MMA helpers (sm_80+ path; no tcgen05) =================
__device__ __forceinline__ uint32_t smem_u32(const void* p) {
    return (uint32_t)__cvta_generic_to_shared(p);
}
// XOR-swizzled byte offset of the 16B chunk (row, c16) in a 128x128 bf16 tile
__device__ __forceinline__ uint32_t sw_off(int row, int c16) {
    return (uint32_t)(row * 256 + ((c16 ^ (row & 7)) << 4));
}
__device__ __forceinline__ void ldx4(uint32_t r[4], uint32_t a) {
    asm volatile("ldmatrix.sync.aligned.m8n8.x4.shared.b16 {%0,%1,%2,%3}, [%4];"
                 : "=r"(r[0]), "=r"(r[1]), "=r"(r[2]), "=r"(r[3]) : "r"(a));
}
__device__ __forceinline__ void mma16816(float c[4], const uint32_t a[4],
                                         uint32_t b0, uint32_t b1) {
    asm volatile("mma.sync.aligned.m16n8k16.row.col.f32.bf16.bf16.f32 "
                 "{%0,%1,%2,%3}, {%4,%5,%6,%7}, {%8,%9}, {%0,%1,%2,%3};"
                 : "+f"(c[0]), "+f"(c[1]), "+f"(c[2]), "+f"(c[3])
                 : "r"(a[0]), "r"(a[1]), "r"(a[2]), "r"(a[3]), "r"(b0), "r"(b1));
}
__device__ __forceinline__ uint32_t pk(__nv_bfloat16 a, __nv_bfloat16 b) {
    return (uint32_t)__bfloat16_as_ushort(a) | ((uint32_t)__bfloat16_as_ushort(b) << 16);
}

// warp tile 32(m) x 64(n), K=128; acc += Ah*Bh + Ah*Bl + Al*Bh
__device__ __forceinline__ void warp_phase(
    uint32_t aH, uint32_t aL, uint32_t bH, uint32_t bL,
    int m_base, int n_base, int lane, float acc[2][8][4])
{
    int r = lane & 15, chs = lane >> 4;
#pragma unroll
    for (int kk = 0; kk < 8; kk++) {
        int c = 2 * kk + chs;
        uint32_t ah[2][4], al[2][4];
#pragma unroll
        for (int mt = 0; mt < 2; mt++) {
            uint32_t off = sw_off(m_base + mt * 16 + r, c);
            ldx4(ah[mt], aH + off);
            ldx4(al[mt], aL + off);
        }
        uint32_t bh[4][4], bl[4][4];
#pragma unroll
        for (int g = 0; g < 4; g++) {
            uint32_t off = sw_off(n_base + g * 16 + r, c);
            ldx4(bh[g], bH + off);
            ldx4(bl[g], bL + off);
        }
#pragma unroll
        for (int mt = 0; mt < 2; mt++)
#pragma unroll
            for (int j = 0; j < 8; j++) {
                int g = j >> 1, p = j & 1;
                mma16816(acc[mt][j], ah[mt], bh[g][p], bh[g][p + 2]);
                mma16816(acc[mt][j], ah[mt], bl[g][p], bl[g][p + 2]);
                mma16816(acc[mt][j], al[mt], bh[g][p], bh[g][p + 2]);
            }
    }
}

// load 128x128 fp32 tile (row guard), split to bf16 hi/lo, store swizzled
__device__ __forceinline__ void load_split(const float* __restrict__ src, int m0, int n,
                                           char* ah, char* al,
                                           const float* __restrict__ rowscale, int tid) {
#pragma unroll
    for (int t = 0; t < 8; t++) {
        int idx = tid + t * 256;
        int row = idx >> 4;
        int c16 = idx & 15;
        int gr = m0 + row;
        float4 v0 = make_float4(0.f, 0.f, 0.f, 0.f), v1 = v0;
        float s = 1.f;
        if (gr < n) {
            const float* p = src + (size_t)gr * D + c16 * 8;
            v0 = *(const float4*)p;
            v1 = *(const float4*)(p + 4);
            if (rowscale) s = rowscale[gr];
        }
        v0.x *= s; v0.y *= s; v0.z *= s; v0.w *= s;
        v1.x *= s; v1.y *= s; v1.z *= s; v1.w *= s;
        float f[8] = {v0.x, v0.y, v0.z, v0.w, v1.x, v1.y, v1.z, v1.w};
        __nv_bfloat16 h[8], l[8];
#pragma unroll
        for (int q = 0; q < 8; q++) {
            h[q] = __float2bfloat16(f[q]);
            l[q] = __float2bfloat16(f[q] - __bfloat162float(h[q]));
        }
        uint32_t off = sw_off(row, c16);
        *(uint4*)(ah + off) = make_uint4(pk(h[0], h[1]), pk(h[2], h[3]), pk(h[4], h[5]), pk(h[6], h[7]));
        *(uint4*)(al + off) = make_uint4(pk(l[0], l[1]), pk(l[2], l[3]), pk(l[4], l[5]), pk(l[6], l[7]));
    }
}

// load 128x128 bf16 tile (row guard) swizzled into smem
__device__ __forceinline__ void load_bf(const __nv_bfloat16* __restrict__ src, int m0,
                                        int nrows, char* dst, int tid) {
#pragma unroll
    for (int t = 0; t < 8; t++) {
        int idx = tid + t * 256;
        int row = idx >> 4;
        int c16 = idx & 15;
        uint4 v = make_uint4(0, 0, 0, 0);
        if (m0 + row < nrows) v = *(const uint4*)(src + (size_t)(m0 + row) * D + c16 * 8);
        *(uint4*)(dst + sw_off(row, c16)) = v;
    }
}

// ================= graph preprocessing (CSR-by-dst counting sort) =================
__global__ void k_zero_small(int n) {
    int i = blockIdx.x * blockDim.x + threadIdx.x;
    if (i < n) { g_deg[i] = 0.f; g_hist[i] = 0; }
}

__global__ void k_hist(const int* __restrict__ src, const int* __restrict__ dst,
                       const float* __restrict__ w, int E) {
    int e = blockIdx.x * blockDim.x + threadIdx.x;
    if (e < E) {
        atomicAdd(&g_deg[src[e]], w[e]);
        atomicAdd(&g_hist[dst[e]], 1);
    }
}

// single-block exclusive scan over g_hist -> g_base, g_cursor
__global__ __launch_bounds__(1024) void k_scan(int n) {
    __shared__ int buf[32];
    __shared__ int carry;
    int tid = threadIdx.x, lane = tid & 31, wid = tid >> 5;
    if (tid == 0) carry = 0;
    __syncthreads();
    for (int c0 = 0; c0 < n; c0 += 1024) {
        int i = c0 + tid;
        int v = (i < n) ? g_hist[i] : 0;
        int x = v;
#pragma unroll
        for (int o = 1; o < 32; o <<= 1) {
            int y = __shfl_up_sync(~0u, x, o);
            if (lane >= o) x += y;
        }
        if (lane == 31) buf[wid] = x;
        __syncthreads();
        if (wid == 0) {
            int s = buf[lane];
#pragma unroll
            for (int o = 1; o < 32; o <<= 1) {
                int y = __shfl_up_sync(~0u, s, o);
                if (lane >= o) s += y;
            }
            buf[lane] = s;
        }
        __syncthreads();
        int incl = x + (wid > 0 ? buf[wid - 1] : 0);
        int excl = incl - v + carry;
        if (i < n) { g_base[i] = excl; g_cursor[i] = excl; }
        __syncthreads();
        if (tid == 1023) carry += incl;
        __syncthreads();
    }
}

__global__ void k_node_prep(int n) {
    int i = blockIdx.x * blockDim.x + threadIdx.x;
    if (i < n) {
        float d = g_deg[i];
        g_dis[i]  = d > 0.f ? rsqrtf(d) : 0.f;
        g_invc[i] = 1.0f / fmaxf((float)g_hist[i], 1.0f);
    }
}

__global__ void k_fill(const int* __restrict__ src, const int* __restrict__ dst,
                       const float* __restrict__ w, int E) {
    int e = blockIdx.x * blockDim.x + threadIdx.x;
    if (e < E) {
        int pos = atomicAdd(&g_cursor[dst[e]], 1);
        g_esrc[pos] = src[e];
        g_ews[pos]  = w[e];
    }
}

// one warp per dst node: register-accumulate Tx1 & msum over edge list, write once
__global__ void k_gather(int n) {
    int wd = (blockIdx.x * blockDim.x + threadIdx.x) >> 5;
    if (wd >= n) return;
    int lane = threadIdx.x & 31;
    int cnt  = g_hist[wd];
    int base = g_base[wd];
    float disd = g_dis[wd];
    float4 at = make_float4(0.f, 0.f, 0.f, 0.f);
    float4 am = make_float4(0.f, 0.f, 0.f, 0.f);
    for (int j = 0; j < cnt; j++) {
        int s   = __ldg(g_esrc + base + j);
        float w = __ldg(g_ews + base + j);
        float cn = -g_dis[s] * w * disd;
        float4 v = *((const float4*)g_xh + (size_t)s * 32 + lane);
        at.x = fmaf(cn, v.x, at.x); at.y = fmaf(cn, v.y, at.y);
        at.z = fmaf(cn, v.z, at.z); at.w = fmaf(cn, v.w, at.w);
        am.x = fmaf(w, v.x, am.x);  am.y = fmaf(w, v.y, am.y);
        am.z = fmaf(w, v.z, am.z);  am.w = fmaf(w, v.w, am.w);
    }
    *((float4*)g_tx1  + (size_t)wd * 32 + lane) = at;
    *((float4*)g_msum + (size_t)wd * 32 + lane) = am;
}

// ================= GEMM kernels =================
#define SM_XH  (131072 + 1024)
#define SM_MID (196608 + 1024)

// xh = x @ Wp^T + bp   (fp32 out to g_xh)
__global__ __launch_bounds__(256) void k_gemm_xh(const float* __restrict__ x,
                                                 const float* __restrict__ Wp,
                                                 const float* __restrict__ bp, int n) {
    extern __shared__ char dsm[];
    char* sb = (char*)(((uintptr_t)dsm + 1023) & ~(uintptr_t)1023);
    int tid = threadIdx.x, wid = tid >> 5, lane = tid & 31;
    int m0 = blockIdx.x * 128;
    int m_base = (wid & 3) * 32, n_base = (wid >> 2) * 64;

    load_split(x, m0, n, sb, sb + 32768, nullptr, tid);
    load_split(Wp, 0, 128, sb + 65536, sb + 98304, nullptr, tid);
    __syncthreads();

    float acc[2][8][4];
#pragma unroll
    for (int a = 0; a < 2; a++)
#pragma unroll
        for (int b = 0; b < 8; b++)
#pragma unroll
            for (int q = 0; q < 4; q++) acc[a][b][q] = 0.f;

    uint32_t base = smem_u32(sb);
    warp_phase(base, base + 32768, base + 65536, base + 98304, m_base, n_base, lane, acc);

    int rr = lane >> 2, cc = 2 * (lane & 3);
#pragma unroll
    for (int mt = 0; mt < 2; mt++) {
        int row = m0 + m_base + mt * 16 + rr;
#pragma unroll
        for (int j = 0; j < 8; j++) {
            int col = n_base + j * 8 + cc;
            float b0 = __ldg(bp + col), b1 = __ldg(bp + col + 1);
            if (row < n)
                *(float2*)(g_xh + (size_t)row * D + col) =
                    make_float2(acc[mt][j][0] + b0, acc[mt][j][1] + b1);
            if (row + 8 < n)
                *(float2*)(g_xh + (size_t)(row + 8) * D + col) =
                    make_float2(acc[mt][j][2] + b0, acc[mt][j][3] + b1);
        }
    }
}

// middle: acc1 = xh@Wc0^T + Tx1@Wc1^T ; acc2 = xh@Wroot^T + mean@Wrel^T
// o12 = lrelu(acc1+bc) + lrelu(acc2+brel) -> bf16 hi/lo
__global__ __launch_bounds__(256) void k_gemm_mid(
    const float* __restrict__ Wc0, const float* __restrict__ Wc1,
    const float* __restrict__ Wroot, const float* __restrict__ Wrel,
    const float* __restrict__ bc, const float* __restrict__ brel, int n) {
    extern __shared__ char dsm[];
    char* sb = (char*)(((uintptr_t)dsm + 1023) & ~(uintptr_t)1023);
    int tid = threadIdx.x, wid = tid >> 5, lane = tid & 31;
    int m0 = blockIdx.x * 128;
    int m_base = (wid & 3) * 32, n_base = (wid >> 2) * 64;

    char* A1h = sb;           char* A1l = sb + 32768;
    char* A2h = sb + 65536;   char* A2l = sb + 98304;
    char* Wh  = sb + 131072;  char* Wl  = sb + 163840;
    uint32_t a1H = smem_u32(A1h), a1L = a1H + 32768;
    uint32_t a2H = a1H + 65536,   a2L = a1H + 98304;
    uint32_t wH  = a1H + 131072,  wL  = a1H + 163840;

    float acc1[2][8][4], acc2[2][8][4];
#pragma unroll
    for (int a = 0; a < 2; a++)
#pragma unroll
        for (int b = 0; b < 8; b++)
#pragma unroll
            for (int q = 0; q < 4; q++) { acc1[a][b][q] = 0.f; acc2[a][b][q] = 0.f; }

    // phase 0: acc1 = xh @ Wc0
    load_split(g_xh,  m0, n, A1h, A1l, nullptr, tid);
    load_split(g_tx1, m0, n, A2h, A2l, nullptr, tid);
    load_split(Wc0, 0, 128, Wh, Wl, nullptr, tid);
    __syncthreads();
    warp_phase(a1H, a1L, wH, wL, m_base, n_base, lane, acc1);
    __syncthreads();

    // phase 1: acc1 += Tx1 @ Wc1
    load_split(Wc1, 0, 128, Wh, Wl, nullptr, tid);
    __syncthreads();
    warp_phase(a2H, a2L, wH, wL, m_base, n_base, lane, acc1);
    __syncthreads();

    // phase 2: acc2 = xh @ Wroot ; reload A2 = mean = msum * invc
    load_split(Wroot, 0, 128, Wh, Wl, nullptr, tid);
    load_split(g_msum, m0, n, A2h, A2l, g_invc, tid);
    __syncthreads();
    warp_phase(a1H, a1L, wH, wL, m_base, n_base, lane, acc2);
    __syncthreads();

    // phase 3: acc2 += mean @ Wrel
    load_split(Wrel, 0, 128, Wh, Wl, nullptr, tid);
    __syncthreads();
    warp_phase(a2H, a2L, wH, wL, m_base, n_base, lane, acc2);

    int rr = lane >> 2, cc = 2 * (lane & 3);
#pragma unroll
    for (int mt = 0; mt < 2; mt++) {
#pragma unroll
        for (int j = 0; j < 8; j++) {
            int col = n_base + j * 8 + cc;
            float c0 = __ldg(bc + col),   c1 = __ldg(bc + col + 1);
            float r0 = __ldg(brel + col), r1 = __ldg(brel + col + 1);
#pragma unroll
            for (int half = 0; half < 2; half++) {
                int row = m0 + m_base + mt * 16 + rr + half * 8;
                if (row < n) {
                    float v1a = acc1[mt][j][2 * half + 0] + c0;
                    float v1b = acc1[mt][j][2 * half + 1] + c1;
                    float v2a = acc2[mt][j][2 * half + 0] + r0;
                    float v2b = acc2[mt][j][2 * half + 1] + r1;
                    v1a = v1a >= 0.f ? v1a : 0.01f * v1a;
                    v1b = v1b >= 0.f ? v1b : 0.01f * v1b;
                    v2a = v2a >= 0.f ? v2a : 0.01f * v2a;
                    v2b = v2b >= 0.f ? v2b : 0.01f * v2b;
                    float oa = v1a + v2a, ob = v1b + v2b;
                    __nv_bfloat16 ha = __float2bfloat16(oa), hb = __float2bfloat16(ob);
                    __nv_bfloat16 la = __float2bfloat16(oa - __bfloat162float(ha));
                    __nv_bfloat16 lb = __float2bfloat16(ob - __bfloat162float(hb));
                    size_t p = (size_t)row * D + col;
                    *(uint32_t*)(g_o12h + p) = pk(ha, hb);
                    *(uint32_t*)(g_o12l + p) = pk(la, lb);
                }
            }
        }
    }
}

// o3 = o12 @ Wl^T + bl  -> fp32 to out region
__global__ __launch_bounds__(256) void k_gemm_fin(const float* __restrict__ Wl,
                                                  const float* __restrict__ bl,
                                                  float* __restrict__ out2, int n) {
    extern __shared__ char dsm[];
    char* sb = (char*)(((uintptr_t)dsm + 1023) & ~(uintptr_t)1023);
    int tid = threadIdx.x, wid = tid >> 5, lane = tid & 31;
    int m0 = blockIdx.x * 128;
    int m_base = (wid & 3) * 32, n_base = (wid >> 2) * 64;

    load_bf(g_o12h, m0, n, sb, tid);
    load_bf(g_o12l, m0, n, sb + 32768, tid);
    load_split(Wl, 0, 128, sb + 65536, sb + 98304, nullptr, tid);
    __syncthreads();

    float acc[2][8][4];
#pragma unroll
    for (int a = 0; a < 2; a++)
#pragma unroll
        for (int b = 0; b < 8; b++)
#pragma unroll
            for (int q = 0; q < 4; q++) acc[a][b][q] = 0.f;

    uint32_t base = smem_u32(sb);
    warp_phase(base, base + 32768, base + 65536, base + 98304, m_base, n_base, lane, acc);

    int rr = lane >> 2, cc = 2 * (lane & 3);
#pragma unroll
    for (int mt = 0; mt < 2; mt++) {
        int row = m0 + m_base + mt * 16 + rr;
#pragma unroll
        for (int j = 0; j < 8; j++) {
            int col = n_base + j * 8 + cc;
            float b0 = __ldg(bl + col), b1 = __ldg(bl + col + 1);
            if (row < n)
                *(float2*)(out2 + (size_t)row * D + col) =
                    make_float2(acc[mt][j][0] + b0, acc[mt][j][1] + b1);
            if (row + 8 < n)
                *(float2*)(out2 + (size_t)(row + 8) * D + col) =
                    make_float2(acc[mt][j][2] + b0, acc[mt][j][3] + b1);
        }
    }
}

// ================= launch =================
extern "C" void kernel_launch(void* const* d_in, const int* in_sizes, int n_in,
                              void* d_out, int out_size) {
    const float* x     = (const float*)d_in[1];
    const int*   ei    = (const int*)  d_in[2];
    const float* ew    = (const float*)d_in[3];
    const float* Wp    = (const float*)d_in[4];
    const float* bp    = (const float*)d_in[5];
    const float* Wc0   = (const float*)d_in[6];
    const float* Wc1   = (const float*)d_in[7];
    const float* bc    = (const float*)d_in[8];
    const float* Wrel  = (const float*)d_in[9];
    const float* brel  = (const float*)d_in[10];
    const float* Wroot = (const float*)d_in[11];
    const float* Wl    = (const float*)d_in[12];
    const float* bl    = (const float*)d_in[13];

    int n = in_sizes[1] / D;
    int E = in_sizes[3];
    float* out = (float*)d_out;

    cudaFuncSetAttribute(k_gemm_xh,  cudaFuncAttributeMaxDynamicSharedMemorySize, SM_XH);
    cudaFuncSetAttribute(k_gemm_mid, cudaFuncAttributeMaxDynamicSharedMemorySize, SM_MID);
    cudaFuncSetAttribute(k_gemm_fin, cudaFuncAttributeMaxDynamicSharedMemorySize, SM_XH);

    // his = x (first half of output)
    cudaMemcpyAsync(out, x, (size_t)n * D * sizeof(float), cudaMemcpyDeviceToDevice, 0);

    int grid = (n + 127) / 128;
    k_zero_small<<<(n + 255) / 256, 256>>>(n);                         // idx 0
    k_hist<<<(E + 255) / 256, 256>>>(ei, ei + E, ew, E);               // idx 1
    k_scan<<<1, 1024>>>(n);                                            // idx 2
    k_gemm_xh<<<grid, 256, SM_XH>>>(x, Wp, bp, n);                     // idx 3 (profiled)
    k_fill<<<(E + 255) / 256, 256>>>(ei, ei + E, ew, E);               // idx 4
    k_node_prep<<<(n + 255) / 256, 256>>>(n);                          // idx 5
    k_gather<<<(n * 32 + 255) / 256, 256>>>(n);                        // idx 6
    k_gemm_mid<<<grid, 256, SM_MID>>>(Wc0, Wc1, Wroot, Wrel, bc, brel, n); // idx 7
    k_gemm_fin<<<grid, 256, SM_XH>>>(Wl, bl, out + (size_t)n * D, n);  // idx 8
}

// round 6
// speedup vs baseline: 1.7909x; 1.2594x over previous
#include <cuda_runtime.h>
#include <cuda_bf16.h>
#include <cstdint>
#include <cstddef>

#define D 128
#define MAXN 50176
#define MAXE 1048576

// ================= global scratch (no allocations allowed) =================
__device__ __align__(16) float g_xh  [(size_t)MAXN * D];           // fp32 xh (gather reads)
__device__ __align__(16) __nv_bfloat16 g_xhh[(size_t)MAXN * D];    // xh hi
__device__ __align__(16) __nv_bfloat16 g_xhl[(size_t)MAXN * D];    // xh lo
__device__ __align__(16) __nv_bfloat16 g_t1h[(size_t)MAXN * D];    // Tx1 hi
__device__ __align__(16) __nv_bfloat16 g_t1l[(size_t)MAXN * D];    // Tx1 lo
__device__ __align__(16) __nv_bfloat16 g_mnh[(size_t)MAXN * D];    // mean hi
__device__ __align__(16) __nv_bfloat16 g_mnl[(size_t)MAXN * D];    // mean lo
__device__ __align__(16) __nv_bfloat16 g_o12h[(size_t)MAXN * D];
__device__ __align__(16) __nv_bfloat16 g_o12l[(size_t)MAXN * D];
__device__ __align__(16) __nv_bfloat16 g_wh[6][D * D];
__device__ __align__(16) __nv_bfloat16 g_wl[6][D * D];
__device__ float g_deg [MAXN];
__device__ float g_dis [MAXN];
__device__ int   g_hist[MAXN];
__device__ int   g_base[MAXN];
__device__ int   g_cursor[MAXN];
__device__ __align__(16) int2 g_epack[MAXE];

enum { WP = 0, WC0, WC1, WREL, WROOT, WLIN };

// ================= helpers =================
__device__ __forceinline__ uint32_t smem_u32(const void* p) {
    return (uint32_t)__cvta_generic_to_shared(p);
}
__device__ __forceinline__ uint32_t sw_off(int row, int c16) {
    return (uint32_t)(row * 256 + ((c16 ^ (row & 7)) << 4));
}
__device__ __forceinline__ void ldx4(uint32_t r[4], uint32_t a) {
    asm volatile("ldmatrix.sync.aligned.m8n8.x4.shared.b16 {%0,%1,%2,%3}, [%4];"
                 : "=r"(r[0]), "=r"(r[1]), "=r"(r[2]), "=r"(r[3]) : "r"(a));
}
__device__ __forceinline__ void mma16816(float c[4], const uint32_t a[4],
                                         uint32_t b0, uint32_t b1) {
    asm volatile("mma.sync.aligned.m16n8k16.row.col.f32.bf16.bf16.f32 "
                 "{%0,%1,%2,%3}, {%4,%5,%6,%7}, {%8,%9}, {%0,%1,%2,%3};"
                 : "+f"(c[0]), "+f"(c[1]), "+f"(c[2]), "+f"(c[3])
                 : "r"(a[0]), "r"(a[1]), "r"(a[2]), "r"(a[3]), "r"(b0), "r"(b1));
}
__device__ __forceinline__ uint32_t pk(__nv_bfloat16 a, __nv_bfloat16 b) {
    return (uint32_t)__bfloat16_as_ushort(a) | ((uint32_t)__bfloat16_as_ushort(b) << 16);
}
__device__ __forceinline__ void cpa16(uint32_t dst, const void* src) {
    asm volatile("cp.async.cg.shared.global [%0], [%1], 16;" :: "r"(dst), "l"(src));
}
#define CPA_COMMIT() asm volatile("cp.async.commit_group;" ::: "memory")
#define CPA_WAIT0()  asm volatile("cp.async.wait_group 0;" ::: "memory")

// async copy of ROWS x 128 bf16 tile, swizzled (sources are device arrays, always in-bounds)
template<int ROWS>
__device__ __forceinline__ void load_async(const __nv_bfloat16* __restrict__ src, int m0,
                                           uint32_t dst, int tid) {
#pragma unroll
    for (int t = 0; t < ROWS * 16 / 256; t++) {
        int idx = tid + t * 256;
        int row = idx >> 4, c16 = idx & 15;
        cpa16(dst + sw_off(row, c16), src + (size_t)(m0 + row) * D + c16 * 8);
    }
}

// register-path load of 64x128 fp32 tile (row guard), split hi/lo, swizzled stores
__device__ __forceinline__ void load_split64(const float* __restrict__ src, int m0, int n,
                                             char* ah, char* al, int tid) {
#pragma unroll
    for (int t = 0; t < 4; t++) {
        int idx = tid + t * 256;
        int row = idx >> 4, c16 = idx & 15;
        int gr = m0 + row;
        float4 v0 = make_float4(0.f, 0.f, 0.f, 0.f), v1 = v0;
        if (gr < n) {
            const float* p = src + (size_t)gr * D + c16 * 8;
            v0 = *(const float4*)p;
            v1 = *(const float4*)(p + 4);
        }
        float f[8] = {v0.x, v0.y, v0.z, v0.w, v1.x, v1.y, v1.z, v1.w};
        __nv_bfloat16 h[8], l[8];
#pragma unroll
        for (int q = 0; q < 8; q++) {
            h[q] = __float2bfloat16(f[q]);
            l[q] = __float2bfloat16(f[q] - __bfloat162float(h[q]));
        }
        uint32_t off = sw_off(row, c16);
        *(uint4*)(ah + off) = make_uint4(pk(h[0],h[1]), pk(h[2],h[3]), pk(h[4],h[5]), pk(h[6],h[7]));
        *(uint4*)(al + off) = make_uint4(pk(l[0],l[1]), pk(l[2],l[3]), pk(l[4],l[5]), pk(l[6],l[7]));
    }
}

// warp tile 32(m) x 32(n), K=128; acc += Ah*Bh + Ah*Bl + Al*Bh
__device__ __forceinline__ void warp_phase32(
    uint32_t aH, uint32_t aL, uint32_t bH, uint32_t bL,
    int m_base, int n_base, int lane, float acc[2][4][4])
{
    int r = lane & 15, chs = lane >> 4;
#pragma unroll
    for (int kk = 0; kk < 8; kk++) {
        int c = 2 * kk + chs;
        uint32_t ah[2][4], al[2][4], bh[2][4], bl[2][4];
#pragma unroll
        for (int mt = 0; mt < 2; mt++) {
            uint32_t off = sw_off(m_base + mt * 16 + r, c);
            ldx4(ah[mt], aH + off);
            ldx4(al[mt], aL + off);
        }
#pragma unroll
        for (int g = 0; g < 2; g++) {
            uint32_t off = sw_off(n_base + g * 16 + r, c);
            ldx4(bh[g], bH + off);
            ldx4(bl[g], bL + off);
        }
#pragma unroll
        for (int mt = 0; mt < 2; mt++)
#pragma unroll
            for (int j = 0; j < 4; j++) {
                int g = j >> 1, p = j & 1;
                mma16816(acc[mt][j], ah[mt], bh[g][p], bh[g][p + 2]);
                mma16816(acc[mt][j], ah[mt], bl[g][p], bl[g][p + 2]);
                mma16816(acc[mt][j], al[mt], bh[g][p], bh[g][p + 2]);
            }
    }
}

// ================= preprocessing =================
__global__ void k_split_w(const float* w0, const float* w1, const float* w2,
                          const float* w3, const float* w4, const float* w5) {
    const float* srcs[6] = {w0, w1, w2, w3, w4, w5};
    int ws = blockIdx.y;
    int i = blockIdx.x * 256 + threadIdx.x;
    float v = srcs[ws][i];
    __nv_bfloat16 h = __float2bfloat16(v);
    g_wh[ws][i] = h;
    g_wl[ws][i] = __float2bfloat16(v - __bfloat162float(h));
}

__global__ void k_zero_small(int n) {
    int i = blockIdx.x * blockDim.x + threadIdx.x;
    if (i < n) { g_deg[i] = 0.f; g_hist[i] = 0; }
}

__global__ void k_hist(const int* __restrict__ src, const int* __restrict__ dst,
                       const float* __restrict__ w, int E) {
    int e = blockIdx.x * blockDim.x + threadIdx.x;
    if (e < E) {
        atomicAdd(&g_deg[src[e]], w[e]);
        atomicAdd(&g_hist[dst[e]], 1);
    }
}

__global__ __launch_bounds__(1024) void k_scan(int n) {
    __shared__ int buf[32];
    __shared__ int carry;
    int tid = threadIdx.x, lane = tid & 31, wid = tid >> 5;
    if (tid == 0) carry = 0;
    __syncthreads();
    for (int c0 = 0; c0 < n; c0 += 1024) {
        int i = c0 + tid;
        int v = (i < n) ? g_hist[i] : 0;
        int x = v;
#pragma unroll
        for (int o = 1; o < 32; o <<= 1) {
            int y = __shfl_up_sync(~0u, x, o);
            if (lane >= o) x += y;
        }
        if (lane == 31) buf[wid] = x;
        __syncthreads();
        if (wid == 0) {
            int s = buf[lane];
#pragma unroll
            for (int o = 1; o < 32; o <<= 1) {
                int y = __shfl_up_sync(~0u, s, o);
                if (lane >= o) s += y;
            }
            buf[lane] = s;
        }
        __syncthreads();
        int incl = x + (wid > 0 ? buf[wid - 1] : 0);
        int excl = incl - v + carry;
        if (i < n) { g_base[i] = excl; g_cursor[i] = excl; }
        __syncthreads();
        if (tid == 1023) carry += incl;
        __syncthreads();
    }
}

__global__ void k_node_prep(int n) {
    int i = blockIdx.x * blockDim.x + threadIdx.x;
    if (i < n) {
        float d = g_deg[i];
        g_dis[i] = d > 0.f ? rsqrtf(d) : 0.f;
    }
}

__global__ void k_fill(const int* __restrict__ src, const int* __restrict__ dst,
                       const float* __restrict__ w, int E) {
    int e = blockIdx.x * blockDim.x + threadIdx.x;
    if (e < E) {
        int pos = atomicAdd(&g_cursor[dst[e]], 1);
        g_epack[pos] = make_int2(src[e], __float_as_int(w[e]));
    }
}

// warp per dst node: accumulate Tx1 & msum; write bf16 hi/lo (mean scaled inline)
__global__ void k_gather(int n) {
    int wd = (blockIdx.x * blockDim.x + threadIdx.x) >> 5;
    if (wd >= n) return;
    int lane = threadIdx.x & 31;
    int cnt = g_hist[wd], base = g_base[wd];
    float disd = g_dis[wd];
    float inv = 1.0f / fmaxf((float)cnt, 1.0f);
    float4 at = make_float4(0.f, 0.f, 0.f, 0.f);
    float4 am = make_float4(0.f, 0.f, 0.f, 0.f);
    int j = 0;
    for (; j + 2 <= cnt; j += 2) {
        int2 e0 = __ldg(g_epack + base + j);
        int2 e1 = __ldg(g_epack + base + j + 1);
        float4 v0 = __ldg((const float4*)g_xh + (size_t)e0.x * 32 + lane);
        float4 v1 = __ldg((const float4*)g_xh + (size_t)e1.x * 32 + lane);
        float w0 = __int_as_float(e0.y), w1 = __int_as_float(e1.y);
        float c0 = -g_dis[e0.x] * w0 * disd;
        float c1 = -g_dis[e1.x] * w1 * disd;
        at.x = fmaf(c0, v0.x, at.x); at.y = fmaf(c0, v0.y, at.y);
        at.z = fmaf(c0, v0.z, at.z); at.w = fmaf(c0, v0.w, at.w);
        am.x = fmaf(w0, v0.x, am.x); am.y = fmaf(w0, v0.y, am.y);
        am.z = fmaf(w0, v0.z, am.z); am.w = fmaf(w0, v0.w, am.w);
        at.x = fmaf(c1, v1.x, at.x); at.y = fmaf(c1, v1.y, at.y);
        at.z = fmaf(c1, v1.z, at.z); at.w = fmaf(c1, v1.w, at.w);
        am.x = fmaf(w1, v1.x, am.x); am.y = fmaf(w1, v1.y, am.y);
        am.z = fmaf(w1, v1.z, am.z); am.w = fmaf(w1, v1.w, am.w);
    }
    if (j < cnt) {
        int2 e0 = __ldg(g_epack + base + j);
        float4 v0 = __ldg((const float4*)g_xh + (size_t)e0.x * 32 + lane);
        float w0 = __int_as_float(e0.y);
        float c0 = -g_dis[e0.x] * w0 * disd;
        at.x = fmaf(c0, v0.x, at.x); at.y = fmaf(c0, v0.y, at.y);
        at.z = fmaf(c0, v0.z, at.z); at.w = fmaf(c0, v0.w, at.w);
        am.x = fmaf(w0, v0.x, am.x); am.y = fmaf(w0, v0.y, am.y);
        am.z = fmaf(w0, v0.z, am.z); am.w = fmaf(w0, v0.w, am.w);
    }
    am.x *= inv; am.y *= inv; am.z *= inv; am.w *= inv;
    float ft[4] = {at.x, at.y, at.z, at.w};
    float fm[4] = {am.x, am.y, am.z, am.w};
    __nv_bfloat16 th[4], tl[4], mh[4], ml[4];
#pragma unroll
    for (int q = 0; q < 4; q++) {
        th[q] = __float2bfloat16(ft[q]);
        tl[q] = __float2bfloat16(ft[q] - __bfloat162float(th[q]));
        mh[q] = __float2bfloat16(fm[q]);
        ml[q] = __float2bfloat16(fm[q] - __bfloat162float(mh[q]));
    }
    size_t p = (size_t)wd * D + lane * 4;
    *(uint2*)(g_t1h + p) = make_uint2(pk(th[0], th[1]), pk(th[2], th[3]));
    *(uint2*)(g_t1l + p) = make_uint2(pk(tl[0], tl[1]), pk(tl[2], tl[3]));
    *(uint2*)(g_mnh + p) = make_uint2(pk(mh[0], mh[1]), pk(mh[2], mh[3]));
    *(uint2*)(g_mnl + p) = make_uint2(pk(ml[0], ml[1]), pk(ml[2], ml[3]));
}

// ================= GEMM kernels =================
// xh/fin smem: Ah@0(16K) Al@16K Wh@32K Wl@64K  = 96KB -> 2 CTA/SM
#define SM_G64 (98304)
// mid smem: A1h@0 A1l@16K A2h@32K A2l@48K  Wa@64K(96K)  Wb@128K(160K) = 192KB
#define SM_MID (196608)

// xh = x @ Wp^T + bp ; writes fp32 g_xh + bf16 hi/lo g_xhh/g_xhl
__global__ __launch_bounds__(256, 2) void k_gemm_xh(const float* __restrict__ x,
                                                    const float* __restrict__ bp, int n) {
    extern __shared__ __align__(256) char sb[];
    int tid = threadIdx.x, wid = tid >> 5, lane = tid & 31;
    int m0 = blockIdx.x * 64;
    int m_base = (wid & 1) * 32, n_base = (wid >> 1) * 32;
    uint32_t base = smem_u32(sb);

    load_async<128>(g_wh[WP], 0, base + 32768, tid);
    load_async<128>(g_wl[WP], 0, base + 65536, tid);
    CPA_COMMIT();
    load_split64(x, m0, n, sb, sb + 16384, tid);
    CPA_WAIT0();
    __syncthreads();

    float acc[2][4][4];
#pragma unroll
    for (int a = 0; a < 2; a++)
#pragma unroll
        for (int b = 0; b < 4; b++)
#pragma unroll
            for (int q = 0; q < 4; q++) acc[a][b][q] = 0.f;

    warp_phase32(base, base + 16384, base + 32768, base + 65536, m_base, n_base, lane, acc);

    int rr = lane >> 2, cc = 2 * (lane & 3);
#pragma unroll
    for (int mt = 0; mt < 2; mt++) {
#pragma unroll
        for (int j = 0; j < 4; j++) {
            int col = n_base + j * 8 + cc;
            float b0 = __ldg(bp + col), b1 = __ldg(bp + col + 1);
#pragma unroll
            for (int half = 0; half < 2; half++) {
                int row = m0 + m_base + mt * 16 + rr + half * 8;
                if (row < n) {
                    float va = acc[mt][j][2 * half + 0] + b0;
                    float vb = acc[mt][j][2 * half + 1] + b1;
                    size_t p = (size_t)row * D + col;
                    *(float2*)(g_xh + p) = make_float2(va, vb);
                    __nv_bfloat16 ha = __float2bfloat16(va), hb = __float2bfloat16(vb);
                    __nv_bfloat16 la = __float2bfloat16(va - __bfloat162float(ha));
                    __nv_bfloat16 lb = __float2bfloat16(vb - __bfloat162float(hb));
                    *(uint32_t*)(g_xhh + p) = pk(ha, hb);
                    *(uint32_t*)(g_xhl + p) = pk(la, lb);
                }
            }
        }
    }
}

// mid: acc1 = xh@Wc0^T + Tx1@Wc1^T ; acc2 = xh@Wroot^T + mean@Wrel^T
// o12 = lrelu(acc1+bc) + lrelu(acc2+brel) -> bf16 hi/lo ; fully cp.async-fed
__global__ __launch_bounds__(256) void k_gemm_mid(const float* __restrict__ bc,
                                                  const float* __restrict__ brel, int n) {
    extern __shared__ __align__(256) char sb[];
    int tid = threadIdx.x, wid = tid >> 5, lane = tid & 31;
    int m0 = blockIdx.x * 64;
    int m_base = (wid & 1) * 32, n_base = (wid >> 1) * 32;
    uint32_t base = smem_u32(sb);
    uint32_t a1H = base,          a1L = base + 16384;
    uint32_t a2H = base + 32768,  a2L = base + 49152;
    uint32_t waH = base + 65536,  waL = base + 98304;
    uint32_t wbH = base + 131072, wbL = base + 163840;

    float acc1[2][4][4], acc2[2][4][4];
#pragma unroll
    for (int a = 0; a < 2; a++)
#pragma unroll
        for (int b = 0; b < 4; b++)
#pragma unroll
            for (int q = 0; q < 4; q++) { acc1[a][b][q] = 0.f; acc2[a][b][q] = 0.f; }

    // stage 0 loads: A1=xh, A2=Tx1, Wa=Wc0
    load_async<64>(g_xhh, m0, a1H, tid);
    load_async<64>(g_xhl, m0, a1L, tid);
    load_async<64>(g_t1h, m0, a2H, tid);
    load_async<64>(g_t1l, m0, a2L, tid);
    load_async<128>(g_wh[WC0], 0, waH, tid);
    load_async<128>(g_wl[WC0], 0, waL, tid);
    CPA_COMMIT();
    CPA_WAIT0();
    __syncthreads();

    // issue Wb=Wc1, compute P0: acc1 += xh@Wc0
    load_async<128>(g_wh[WC1], 0, wbH, tid);
    load_async<128>(g_wl[WC1], 0, wbL, tid);
    CPA_COMMIT();
    warp_phase32(a1H, a1L, waH, waL, m_base, n_base, lane, acc1);
    CPA_WAIT0();
    __syncthreads();

    // issue Wa=Wroot, compute P1: acc1 += Tx1@Wc1
    load_async<128>(g_wh[WROOT], 0, waH, tid);
    load_async<128>(g_wl[WROOT], 0, waL, tid);
    CPA_COMMIT();
    warp_phase32(a2H, a2L, wbH, wbL, m_base, n_base, lane, acc1);
    CPA_WAIT0();
    __syncthreads();

    // issue A2=mean + Wb=Wrel, compute P2: acc2 += xh@Wroot
    load_async<64>(g_mnh, m0, a2H, tid);
    load_async<64>(g_mnl, m0, a2L, tid);
    load_async<128>(g_wh[WREL], 0, wbH, tid);
    load_async<128>(g_wl[WREL], 0, wbL, tid);
    CPA_COMMIT();
    warp_phase32(a1H, a1L, waH, waL, m_base, n_base, lane, acc2);
    CPA_WAIT0();
    __syncthreads();

    // compute P3: acc2 += mean@Wrel
    warp_phase32(a2H, a2L, wbH, wbL, m_base, n_base, lane, acc2);

    int rr = lane >> 2, cc = 2 * (lane & 3);
#pragma unroll
    for (int mt = 0; mt < 2; mt++) {
#pragma unroll
        for (int j = 0; j < 4; j++) {
            int col = n_base + j * 8 + cc;
            float c0 = __ldg(bc + col),   c1 = __ldg(bc + col + 1);
            float r0 = __ldg(brel + col), r1 = __ldg(brel + col + 1);
#pragma unroll
            for (int half = 0; half < 2; half++) {
                int row = m0 + m_base + mt * 16 + rr + half * 8;
                if (row < n) {
                    float v1a = acc1[mt][j][2 * half + 0] + c0;
                    float v1b = acc1[mt][j][2 * half + 1] + c1;
                    float v2a = acc2[mt][j][2 * half + 0] + r0;
                    float v2b = acc2[mt][j][2 * half + 1] + r1;
                    v1a = v1a >= 0.f ? v1a : 0.01f * v1a;
                    v1b = v1b >= 0.f ? v1b : 0.01f * v1b;
                    v2a = v2a >= 0.f ? v2a : 0.01f * v2a;
                    v2b = v2b >= 0.f ? v2b : 0.01f * v2b;
                    float oa = v1a + v2a, ob = v1b + v2b;
                    __nv_bfloat16 ha = __float2bfloat16(oa), hb = __float2bfloat16(ob);
                    __nv_bfloat16 la = __float2bfloat16(oa - __bfloat162float(ha));
                    __nv_bfloat16 lb = __float2bfloat16(ob - __bfloat162float(hb));
                    size_t p = (size_t)row * D + col;
                    *(uint32_t*)(g_o12h + p) = pk(ha, hb);
                    *(uint32_t*)(g_o12l + p) = pk(la, lb);
                }
            }
        }
    }
}

// o3 = o12 @ Wl^T + bl -> fp32 ; fully cp.async-fed
__global__ __launch_bounds__(256, 2) void k_gemm_fin(const float* __restrict__ bl,
                                                     float* __restrict__ out2, int n) {
    extern __shared__ __align__(256) char sb[];
    int tid = threadIdx.x, wid = tid >> 5, lane = tid & 31;
    int m0 = blockIdx.x * 64;
    int m_base = (wid & 1) * 32, n_base = (wid >> 1) * 32;
    uint32_t base = smem_u32(sb);

    load_async<64>(g_o12h, m0, base, tid);
    load_async<64>(g_o12l, m0, base + 16384, tid);
    load_async<128>(g_wh[WLIN], 0, base + 32768, tid);
    load_async<128>(g_wl[WLIN], 0, base + 65536, tid);
    CPA_COMMIT();
    CPA_WAIT0();
    __syncthreads();

    float acc[2][4][4];
#pragma unroll
    for (int a = 0; a < 2; a++)
#pragma unroll
        for (int b = 0; b < 4; b++)
#pragma unroll
            for (int q = 0; q < 4; q++) acc[a][b][q] = 0.f;

    warp_phase32(base, base + 16384, base + 32768, base + 65536, m_base, n_base, lane, acc);

    int rr = lane >> 2, cc = 2 * (lane & 3);
#pragma unroll
    for (int mt = 0; mt < 2; mt++) {
#pragma unroll
        for (int j = 0; j < 4; j++) {
            int col = n_base + j * 8 + cc;
            float b0 = __ldg(bl + col), b1 = __ldg(bl + col + 1);
#pragma unroll
            for (int half = 0; half < 2; half++) {
                int row = m0 + m_base + mt * 16 + rr + half * 8;
                if (row < n)
                    *(float2*)(out2 + (size_t)row * D + col) =
                        make_float2(acc[mt][j][2 * half + 0] + b0,
                                    acc[mt][j][2 * half + 1] + b1);
            }
        }
    }
}

// ================= launch =================
extern "C" void kernel_launch(void* const* d_in, const int* in_sizes, int n_in,
                              void* d_out, int out_size) {
    const float* x     = (const float*)d_in[1];
    const int*   ei    = (const int*)  d_in[2];
    const float* ew    = (const float*)d_in[3];
    const float* Wp    = (const float*)d_in[4];
    const float* bp    = (const float*)d_in[5];
    const float* Wc0   = (const float*)d_in[6];
    const float* Wc1   = (const float*)d_in[7];
    const float* bc    = (const float*)d_in[8];
    const float* Wrel  = (const float*)d_in[9];
    const float* brel  = (const float*)d_in[10];
    const float* Wroot = (const float*)d_in[11];
    const float* Wl    = (const float*)d_in[12];
    const float* bl    = (const float*)d_in[13];

    int n = in_sizes[1] / D;
    int E = in_sizes[3];
    float* out = (float*)d_out;

    cudaFuncSetAttribute(k_gemm_xh,  cudaFuncAttributeMaxDynamicSharedMemorySize, SM_G64);
    cudaFuncSetAttribute(k_gemm_mid, cudaFuncAttributeMaxDynamicSharedMemorySize, SM_MID);
    cudaFuncSetAttribute(k_gemm_fin, cudaFuncAttributeMaxDynamicSharedMemorySize, SM_G64);

    // his = x (first half of output)
    cudaMemcpyAsync(out, x, (size_t)n * D * sizeof(float), cudaMemcpyDeviceToDevice, 0);

    int g64 = (n + 63) / 64;
    k_split_w<<<dim3(64, 6), 256>>>(Wp, Wc0, Wc1, Wrel, Wroot, Wl);    // k0
    k_zero_small<<<(n + 255) / 256, 256>>>(n);                         // k1
    k_hist<<<(E + 255) / 256, 256>>>(ei, ei + E, ew, E);               // k2
    k_gemm_xh<<<g64, 256, SM_G64>>>(x, bp, n);                         // k3 (profiled)
    k_scan<<<1, 1024>>>(n);                                            // k4
    k_fill<<<(E + 255) / 256, 256>>>(ei, ei + E, ew, E);               // k5
    k_node_prep<<<(n + 255) / 256, 256>>>(n);                          // k6
    k_gather<<<(n * 32 + 255) / 256, 256>>>(n);                        // k7
    k_gemm_mid<<<g64, 256, SM_MID>>>(bc, brel, n);                     // k8
    k_gemm_fin<<<g64, 256, SM_G64>>>(bl, out + (size_t)n * D, n);      // k9
}